// round 10
// baseline (speedup 1.0000x reference)
#include <cuda_runtime.h>
#include <math.h>

// Problem dims (fixed)
#define Bsz   128
#define Tlen  512
#define Isz   256
#define Hsz   512
#define Osz   256

// Pod decomposition: 16 pods = 16 HW clusters of 8 CTAs; each pod owns 8
// batches; each block owns 64 h-rows of W_hh (128KB fp32 in smem).
#define PODS  16
#define PODB  8      // blocks per pod (= cluster size)
#define PB    8      // batches per pod
#define NBT   8      // xp batch tiles (of 16)

// Packed f32x2 helpers (ptxas never emits FFMA2 from C++; inline PTX required)
#define FMA2(acc, a, b) \
    asm("fma.rn.f32x2 %0, %1, %2, %0;" : "+l"(acc) : "l"(a), "l"(b))
#define ADD2(d, a, b) \
    asm("add.rn.f32x2 %0, %1, %2;" : "=l"(d) : "l"(a), "l"(b))
#define PACK2(d, lo, hi) \
    asm("mov.b64 %0, {%1, %2};" : "=l"(d) : "f"(lo), "f"(hi))
#define UNPACK2(lo, hi, v) \
    asm("mov.b64 {%0, %1}, %2;" : "=f"(lo), "=f"(hi) : "l"(v))

#define CLUSTER_ARRIVE() asm volatile("barrier.cluster.arrive.aligned;" ::: "memory")
#define CLUSTER_WAIT()   asm volatile("barrier.cluster.wait.aligned;" ::: "memory")

typedef unsigned long long u64;

// Scratch (device globals; no runtime allocation)
__device__ float g_xp[(size_t)Tlen * PODS * Hsz * PB]; // [t][pod][h][8]
__device__ float g_h[2][PODS * Hsz * PB];              // [parity][pod][k][8]

// ---------------------------------------------------------------------------
// x_proj: xp[t][pod][h][b] = sum_i inputs[b][t][i]*W_ih[h][i] + b_ih[h]+b_hh[h]
// ---------------------------------------------------------------------------
#define TQ  8
#define XSROW 257

__global__ void __launch_bounds__(256) xp_kernel(
    const float* __restrict__ inputs, const float* __restrict__ W_ih,
    const float* __restrict__ b_ih,   const float* __restrict__ b_hh)
{
    extern __shared__ float smem[];
    float* Wt  = smem;                              // [256][32]: Wt[i][j]=W_ih[h0+j][i]
    u64*   xs2 = (u64*)(smem + 8192);               // [16][257]: xs2[b][i]={x,x}
    u64*   red = (u64*)(smem + 8192 + 2 * 16 * XSROW);  // [4][16][16]
    const u64* Wtu = (const u64*)Wt;

    const int tq = blockIdx.x, bt = blockIdx.y, ht = blockIdx.z;
    const int h0 = ht * 32, b0 = bt * 16;
    const int tid = threadIdx.x;

    // Stage W_ih tile transposed (once)
    {
        const int lane_j = tid & 31, qb = tid >> 5;          // qb 0..7
        for (int r = 0; r < 8; r++) {
            int q = qb + 8 * r;                              // 0..63
            float4 w = *(const float4*)&W_ih[(h0 + lane_j) * Isz + 4 * q];
            Wt[(4*q+0)*32 + lane_j] = w.x;
            Wt[(4*q+1)*32 + lane_j] = w.y;
            Wt[(4*q+2)*32 + lane_j] = w.z;
            Wt[(4*q+3)*32 + lane_j] = w.w;
        }
    }

    const int bg = tid & 7, hg = (tid >> 3) & 7, is = tid >> 6;  // I-split 4
    const int pb = tid & 15, php = tid >> 4;                     // phase-2 roles
    const int pod = bt * 2 + (pb >> 3), bi = pb & 7;
    const float pbias0 = b_ih[h0 + php*2 + 0] + b_hh[h0 + php*2 + 0];
    const float pbias1 = b_ih[h0 + php*2 + 1] + b_hh[h0 + php*2 + 1];

    for (int tt = 0; tt < TQ; tt++) {
        const int t = tq * TQ + tt;
        __syncthreads();   // xs2/red reuse; covers Wt on first iter
        for (int j = 0; j < 4; j++) {
            int idx = tid + 256 * j;                 // 1024 float4 loads
            int r = idx >> 6, q = idx & 63;
            float4 x = *(const float4*)&inputs[((size_t)(b0 + r) * Tlen + t) * Isz + 4 * q];
            u64 p0, p1, p2, p3;
            PACK2(p0, x.x, x.x); PACK2(p1, x.y, x.y);
            PACK2(p2, x.z, x.z); PACK2(p3, x.w, x.w);
            u64* dst = &xs2[r * XSROW + 4 * q];
            dst[0] = p0; dst[1] = p1; dst[2] = p2; dst[3] = p3;
        }
        __syncthreads();

        u64 a00 = 0, a10 = 0, a01 = 0, a11 = 0;
        const u64* xr0 = &xs2[(2 * bg + 0) * XSROW + is * 64];
        const u64* xr1 = &xs2[(2 * bg + 1) * XSROW + is * 64];
        const u64* wr  = &Wtu[(is * 64) * 16 + hg * 2];
        #pragma unroll 8
        for (int ii = 0; ii < 64; ii++) {
            ulonglong2 w = *(const ulonglong2*)&wr[ii * 16];
            u64 x0 = xr0[ii];
            u64 x1 = xr1[ii];
            FMA2(a00, w.x, x0);
            FMA2(a10, w.y, x0);
            FMA2(a01, w.x, x1);
            FMA2(a11, w.y, x1);
        }
        u64* rb = &red[is * 256 + (hg * 2) * 16 + bg * 2];
        rb[0]  = a00;
        rb[16] = a10;
        rb[1]  = a01;
        rb[17] = a11;
        __syncthreads();

        u64 s, u;
        ADD2(s, red[0*256 + php*16 + pb], red[1*256 + php*16 + pb]);
        ADD2(u, red[2*256 + php*16 + pb], red[3*256 + php*16 + pb]);
        ADD2(s, s, u);
        float v0, v1; UNPACK2(v0, v1, s);
        float* dst = &g_xp[(((size_t)t * PODS + pod) * Hsz + h0 + php * 2) * PB + bi];
        dst[0]  = v0 + pbias0;
        dst[PB] = v1 + pbias1;
    }
}

// ---------------------------------------------------------------------------
// Persistent recurrence + fused init + fused readout. HW clusters of 8 CTAs.
// 128 blocks = 16 pods; 512 threads. FMA2 GEMM: thread tile 8h x 4b, K-split 32.
// Per k: 4 LDS.128 + 16 FMA2 (vs 3 + 32 FFMA before).
// smem: Wt[512][64] f32 (128KB) + hs2[512][8] u64 {h,h} (32KB) + red2[32][32][8] u64 (64KB)
// ---------------------------------------------------------------------------
__global__ void __launch_bounds__(512) __cluster_dims__(PODB, 1, 1) rnn_kernel(
    const float* __restrict__ W_hh, const float* __restrict__ h0g,
    const float* __restrict__ W_out, const float* __restrict__ b_out,
    float* __restrict__ out)
{
    extern __shared__ float smem[];
    float* Wt   = smem;                        // [512][64]: Wt[k][j]=W_hh[h0+j][k]
    u64*   hs2  = (u64*)(smem + Hsz * 64);     // [512][8]: {h[k][b], h[k][b]}
    u64*   red2 = (u64*)(smem + Hsz * 64 + Hsz * PB * 2);  // [32ks][32hp][8b]
    const u64* Wtu = (const u64*)Wt;
    float* hs2f = (float*)hs2;
    const float* redf = (const float*)red2;

    const int blk = blockIdx.x;
    const int pod = blk >> 3, ht = blk & 7;
    const int h0 = ht * 64;
    const int tid = threadIdx.x;

    // Stage this block's 64-row W_hh slice once (reused all 512 steps)
    {
        const int j = tid & 63, qg = tid >> 6;               // qg 0..7
        for (int q = qg; q < 128; q += 8) {
            float4 w = *(const float4*)&W_hh[(h0 + j) * Hsz + 4 * q];
            Wt[(4*q+0)*64 + j] = w.x;
            Wt[(4*q+1)*64 + j] = w.y;
            Wt[(4*q+2)*64 + j] = w.z;
            Wt[(4*q+3)*64 + j] = w.w;
        }
    }

    // GEMM roles: ks 0..31 (16 k each), hg 0..7 (8 h-rows = 4 h-pairs), bg 0..1 (4 b)
    const int ks = tid >> 4;
    const int hg = (tid >> 1) & 7;
    const int bg = tid & 1;
    // Phase-2/epilogue roles: h = tid>>3, b = tid&7
    const int ph = tid >> 3, pb = tid & 7;
    const float invT = 1.0f / 512.0f;

    for (int t = 0; t < Tlen; t++) {
        if (t == 0) {
            // Fused hinit: hs2[k][b] = {h0[k], h0[k]}
            float v = h0g[tid];                      // tid == k
            u64 p; PACK2(p, v, v);
            ulonglong2 pp; pp.x = p; pp.y = p;
            ulonglong2* dst = (ulonglong2*)&hs2[tid * PB];
            dst[0] = pp; dst[1] = pp; dst[2] = pp; dst[3] = pp;
        } else {
            // Stage pod h slice (16KB) from L2, replicated into hs2
            const float4* hsrc = (const float4*)(g_h[t & 1] + pod * (Hsz * PB));
            for (int j2 = 0; j2 < 2; j2++) {
                int idx = tid + 512 * j2;                    // 1024 float4
                float4 v = __ldcg(hsrc + idx);
                u64 p0, p1, p2, p3;
                PACK2(p0, v.x, v.x); PACK2(p1, v.y, v.y);
                PACK2(p2, v.z, v.z); PACK2(p3, v.w, v.w);
                ulonglong2* dst = (ulonglong2*)&hs2[idx * 4];
                ulonglong2 q0; q0.x = p0; q0.y = p1;
                ulonglong2 q1; q1.x = p2; q1.y = p3;
                dst[0] = q0; dst[1] = q1;
            }
        }
        // Prefetch xp for this thread's epilogue output (hidden by GEMM)
        const float xp = __ldg(&g_xp[(((size_t)t * PODS + pod) * Hsz + h0) * PB + tid]);
        __syncthreads();

        // GEMM slice: acc[4 hpairs][4 b] as f32x2; 4 LDS.128 + 16 FMA2 per k
        u64 a0[4], a1[4], a2[4], a3[4];
        #pragma unroll
        for (int j = 0; j < 4; j++) { a0[j] = 0; a1[j] = 0; a2[j] = 0; a3[j] = 0; }

        const u64* wr = &Wtu[(ks * 16) * 32 + hg * 4];
        const u64* hr = &hs2[(ks * 16) * PB + bg * 4];
        #pragma unroll
        for (int kk = 0; kk < 16; kk++) {
            ulonglong2 wA = *(const ulonglong2*)&wr[kk * 32];      // hpairs 0,1
            ulonglong2 wB = *(const ulonglong2*)&wr[kk * 32 + 2];  // hpairs 2,3
            ulonglong2 hA = *(const ulonglong2*)&hr[kk * PB];      // b0,b1 replicated
            ulonglong2 hB = *(const ulonglong2*)&hr[kk * PB + 2];  // b2,b3
            FMA2(a0[0], wA.x, hA.x); FMA2(a0[1], wA.x, hA.y);
            FMA2(a0[2], wA.x, hB.x); FMA2(a0[3], wA.x, hB.y);
            FMA2(a1[0], wA.y, hA.x); FMA2(a1[1], wA.y, hA.y);
            FMA2(a1[2], wA.y, hB.x); FMA2(a1[3], wA.y, hB.y);
            FMA2(a2[0], wB.x, hA.x); FMA2(a2[1], wB.x, hA.y);
            FMA2(a2[2], wB.x, hB.x); FMA2(a2[3], wB.x, hB.y);
            FMA2(a3[0], wB.y, hA.x); FMA2(a3[1], wB.y, hA.y);
            FMA2(a3[2], wB.y, hB.x); FMA2(a3[3], wB.y, hB.y);
        }
        // Store partials: red2[ks][hg*4+hp][bg*4 + b]
        {
            u64* rb = &red2[ks * 256 + (hg * 4) * PB + bg * 4];
            ulonglong2 s0; s0.x = a0[0]; s0.y = a0[1];
            ulonglong2 s1; s1.x = a0[2]; s1.y = a0[3];
            *(ulonglong2*)&rb[0] = s0;       *(ulonglong2*)&rb[2] = s1;
            s0.x = a1[0]; s0.y = a1[1]; s1.x = a1[2]; s1.y = a1[3];
            *(ulonglong2*)&rb[PB] = s0;      *(ulonglong2*)&rb[PB + 2] = s1;
            s0.x = a2[0]; s0.y = a2[1]; s1.x = a2[2]; s1.y = a2[3];
            *(ulonglong2*)&rb[2*PB] = s0;    *(ulonglong2*)&rb[2*PB + 2] = s1;
            s0.x = a3[0]; s0.y = a3[1]; s1.x = a3[2]; s1.y = a3[3];
            *(ulonglong2*)&rb[3*PB] = s0;    *(ulonglong2*)&rb[3*PB + 2] = s1;
        }
        __syncthreads();

        // Phase 2: reduce 32 K-splits (float view; conflict-free), epilogue
        {
            // float index within one ks slab (512 floats): ((ph>>1)*8+pb)*2 + (ph&1)
            const int fidx = (((ph >> 1) * PB + pb) << 1) + (ph & 1);
            const float* rp = &redf[fidx];
            float s0 = 0.f, s1 = 0.f, s2 = 0.f, s3 = 0.f;
            #pragma unroll
            for (int k2 = 0; k2 < 8; k2++) {
                s0 += rp[(4*k2+0) * 512];
                s1 += rp[(4*k2+1) * 512];
                s2 += rp[(4*k2+2) * 512];
                s3 += rp[(4*k2+3) * 512];
            }
            float v = (s0 + s1) + (s2 + s3);
            float hp = hs2f[(h0 * PB + tid) * 2];    // .lo of replicated pair
            float hnew = hp + tanhf(v + xp) * invT;
            g_h[(t + 1) & 1][pod * (Hsz * PB) + h0 * PB + tid] = hnew;
        }

        // Cluster barrier: arrive releases our g_h stores; wait acquires peers'.
        // Subsumes end-of-step __syncthreads (all CTA threads must arrive).
        CLUSTER_ARRIVE();
        CLUSTER_WAIT();
    }

    // ---- Fused readout: out[b][o] = sum_k h_last[k][b]*W_out[o][k] + b_out[o]
    const int o0 = ht * 32;
    float* hsf = (float*)hs2;                        // reuse as plain [512][8]
    {
        // Final h (T=512 even -> parity 0); cluster-synced by last barrier.
        const float4* hsrc = (const float4*)(g_h[0] + pod * (Hsz * PB));
        for (int j2 = 0; j2 < 2; j2++) {
            int idx = tid + 512 * j2;
            ((float4*)hsf)[idx] = __ldcg(hsrc + idx);
        }
        // W_out slice transposed into (freed) Wt region: Wo[k][32]
        const int lane_j = tid & 31, qg = tid >> 5;          // qg 0..15
        for (int q = qg; q < 128; q += 16) {
            float4 w = *(const float4*)&W_out[(o0 + lane_j) * Hsz + 4 * q];
            Wt[(4*q+0)*32 + lane_j] = w.x;
            Wt[(4*q+1)*32 + lane_j] = w.y;
            Wt[(4*q+2)*32 + lane_j] = w.z;
            Wt[(4*q+3)*32 + lane_j] = w.w;
        }
    }
    __syncthreads();
    if (tid < 256) {
        const int b_ = tid & 7, og = tid >> 3;       // og 0..31
        float acc = 0.f;
        #pragma unroll 8
        for (int k = 0; k < Hsz; k++) {
            acc += hsf[k * PB + b_] * Wt[k * 32 + og];
        }
        out[(pod * PB + b_) * Osz + o0 + og] = acc + b_out[o0 + og];
    }
}

// ---------------------------------------------------------------------------
extern "C" void kernel_launch(void* const* d_in, const int* in_sizes, int n_in,
                              void* d_out, int out_size)
{
    const float* inputs = (const float*)d_in[0];
    const float* W_ih   = (const float*)d_in[1];
    const float* b_ih   = (const float*)d_in[2];
    const float* W_hh   = (const float*)d_in[3];
    const float* b_hh   = (const float*)d_in[4];
    const float* W_out  = (const float*)d_in[5];
    const float* b_out  = (const float*)d_in[6];
    const float* h0     = (const float*)d_in[7];
    float* out = (float*)d_out;

    const int SMEM_XP  = 8192 * 4 + 2 * 16 * XSROW * 8 + 1024 * 8;        // 73856 B
    const int SMEM_RNN = Hsz * 64 * 4 + Hsz * PB * 8 + 32 * 32 * PB * 8;  // 229376 B
    cudaFuncSetAttribute(xp_kernel,  cudaFuncAttributeMaxDynamicSharedMemorySize, SMEM_XP);
    cudaFuncSetAttribute(rnn_kernel, cudaFuncAttributeMaxDynamicSharedMemorySize, SMEM_RNN);

    xp_kernel<<<dim3(Tlen / TQ, NBT, Hsz / 32), 256, SMEM_XP>>>(inputs, W_ih, b_ih, b_hh);
    rnn_kernel<<<PODS * PODB, 512, SMEM_RNN>>>(W_hh, h0, W_out, b_out, out);
}

// round 12
// speedup vs baseline: 1.5112x; 1.5112x over previous
#include <cuda_runtime.h>
#include <math.h>

// Problem dims (fixed)
#define Bsz   128
#define Tlen  512
#define Isz   256
#define Hsz   512
#define Osz   256

// Pod decomposition: 16 independent pods x 8 blocks; each pod owns 8 batches,
// each block owns 64 h-rows of W_hh (128KB fp32 in smem).
#define PODS  16
#define PODB  8      // blocks per pod
#define PB    8      // batches per pod
#define NBT   8      // xp batch tiles (of 16)

// Packed f32x2 helpers (ptxas never emits FFMA2 from C++; inline PTX required)
#define FMA2(acc, a, b) \
    asm("fma.rn.f32x2 %0, %1, %2, %0;" : "+l"(acc) : "l"(a), "l"(b))
#define ADD2(d, a, b) \
    asm("add.rn.f32x2 %0, %1, %2;" : "=l"(d) : "l"(a), "l"(b))
#define PACK2(d, lo, hi) \
    asm("mov.b64 %0, {%1, %2};" : "=l"(d) : "f"(lo), "f"(hi))
#define UNPACK2(lo, hi, v) \
    asm("mov.b64 {%0, %1}, %2;" : "=f"(lo), "=f"(hi) : "l"(v))

typedef unsigned long long u64;

// Scratch (device globals; no runtime allocation)
__device__ float    g_xp[(size_t)Tlen * PODS * Hsz * PB]; // [t][pod][h][8]
__device__ u64      g_h2[2][PODS * Hsz * PB];             // [parity][pod][k][8] as {h,h}
__device__ unsigned g_pbar_count[PODS * 32];              // 128B-padded per pod
__device__ unsigned g_pbar_gen[PODS * 32];

// ---------------------------------------------------------------------------
// x_proj: xp[t][pod][h][b] = sum_i inputs[b][t][i]*W_ih[h][i] + b_ih[h]+b_hh[h]
// ---------------------------------------------------------------------------
#define TQ  8
#define XSROW 257

__global__ void __launch_bounds__(256) xp_kernel(
    const float* __restrict__ inputs, const float* __restrict__ W_ih,
    const float* __restrict__ b_ih,   const float* __restrict__ b_hh)
{
    extern __shared__ float smem[];
    float* Wt  = smem;                              // [256][32]: Wt[i][j]=W_ih[h0+j][i]
    u64*   xs2 = (u64*)(smem + 8192);               // [16][257]: xs2[b][i]={x,x}
    u64*   red = (u64*)(smem + 8192 + 2 * 16 * XSROW);  // [4][16][16]
    const u64* Wtu = (const u64*)Wt;

    const int tq = blockIdx.x, bt = blockIdx.y, ht = blockIdx.z;
    const int h0 = ht * 32, b0 = bt * 16;
    const int tid = threadIdx.x;

    // Stage W_ih tile transposed (once)
    {
        const int lane_j = tid & 31, qb = tid >> 5;          // qb 0..7
        for (int r = 0; r < 8; r++) {
            int q = qb + 8 * r;                              // 0..63
            float4 w = *(const float4*)&W_ih[(h0 + lane_j) * Isz + 4 * q];
            Wt[(4*q+0)*32 + lane_j] = w.x;
            Wt[(4*q+1)*32 + lane_j] = w.y;
            Wt[(4*q+2)*32 + lane_j] = w.z;
            Wt[(4*q+3)*32 + lane_j] = w.w;
        }
    }

    const int bg = tid & 7, hg = (tid >> 3) & 7, is = tid >> 6;  // I-split 4
    const int pb = tid & 15, php = tid >> 4;                     // phase-2 roles
    const int pod = bt * 2 + (pb >> 3), bi = pb & 7;
    const float pbias0 = b_ih[h0 + php*2 + 0] + b_hh[h0 + php*2 + 0];
    const float pbias1 = b_ih[h0 + php*2 + 1] + b_hh[h0 + php*2 + 1];

    for (int tt = 0; tt < TQ; tt++) {
        const int t = tq * TQ + tt;
        __syncthreads();   // xs2/red reuse; covers Wt on first iter
        for (int j = 0; j < 4; j++) {
            int idx = tid + 256 * j;                 // 1024 float4 loads
            int r = idx >> 6, q = idx & 63;
            float4 x = *(const float4*)&inputs[((size_t)(b0 + r) * Tlen + t) * Isz + 4 * q];
            u64 p0, p1, p2, p3;
            PACK2(p0, x.x, x.x); PACK2(p1, x.y, x.y);
            PACK2(p2, x.z, x.z); PACK2(p3, x.w, x.w);
            u64* dst = &xs2[r * XSROW + 4 * q];
            dst[0] = p0; dst[1] = p1; dst[2] = p2; dst[3] = p3;
        }
        __syncthreads();

        u64 a00 = 0, a10 = 0, a01 = 0, a11 = 0;
        const u64* xr0 = &xs2[(2 * bg + 0) * XSROW + is * 64];
        const u64* xr1 = &xs2[(2 * bg + 1) * XSROW + is * 64];
        const u64* wr  = &Wtu[(is * 64) * 16 + hg * 2];
        #pragma unroll 8
        for (int ii = 0; ii < 64; ii++) {
            ulonglong2 w = *(const ulonglong2*)&wr[ii * 16];
            u64 x0 = xr0[ii];
            u64 x1 = xr1[ii];
            FMA2(a00, w.x, x0);
            FMA2(a10, w.y, x0);
            FMA2(a01, w.x, x1);
            FMA2(a11, w.y, x1);
        }
        u64* rb = &red[is * 256 + (hg * 2) * 16 + bg * 2];
        rb[0]  = a00;
        rb[16] = a10;
        rb[1]  = a01;
        rb[17] = a11;
        __syncthreads();

        u64 s, u;
        ADD2(s, red[0*256 + php*16 + pb], red[1*256 + php*16 + pb]);
        ADD2(u, red[2*256 + php*16 + pb], red[3*256 + php*16 + pb]);
        ADD2(s, s, u);
        float v0, v1; UNPACK2(v0, v1, s);
        float* dst = &g_xp[(((size_t)t * PODS + pod) * Hsz + h0 + php * 2) * PB + bi];
        dst[0]  = v0 + pbias0;
        dst[PB] = v1 + pbias1;
    }
}

// ---------------------------------------------------------------------------
// Persistent recurrence + fused init + fused readout. Atomic pod barrier.
// 128 blocks = 16 pods x 8; 512 threads. FMA2 GEMM: roles ks16 x hg8 x bg4,
// thread tile 8h x 2b over 32 k. Per k: 3 LDS.128 + 8 FMA2.
// smem: Wt[512][64] f32 half-split layout (128KB) + hs2[512][8] u64 {h,h}
//       (32KB) + red[16 ks][32 hp][9 pad] u64 (36KB) = 196KB.
// Partials stored as ST.64 (odd-row padding forbids ST.128 alignment).
// ---------------------------------------------------------------------------
#define REDROW 9                       // u64 per hp-row (padded: kills 8-way conflict)
#define REDSLAB (32 * REDROW)          // 288 u64 per ks slab

__global__ void __launch_bounds__(512) rnn_kernel(
    const float* __restrict__ W_hh, const float* __restrict__ h0g,
    const float* __restrict__ W_out, const float* __restrict__ b_out,
    float* __restrict__ out)
{
    extern __shared__ float smem[];
    float* Wt  = smem;                          // [512][64] half-split (see below)
    u64*   hs2 = (u64*)(smem + Hsz * 64);       // [512][8]: {h[k][b], h[k][b]}
    u64*   red = (u64*)(smem + Hsz * 64 + Hsz * PB * 2);  // [16][32][9]
    const u64* Wtu = (const u64*)Wt;
    float* hs2f = (float*)hs2;
    const float* redf = (const float*)red;

    const int blk = blockIdx.x;
    const int pod = blk >> 3, ht = blk & 7;
    const int h0 = ht * 64;
    const int tid = threadIdx.x;

    // Stage W_hh slice once. Per-k float layout (so each warp w-load spans a
    // contiguous 128B, conflict-free):
    //   j (0..63) -> fidx = ((j&7)>>2)*32 + (j>>3)*4 + (((j&7)>>1)&1)*2 + (j&1)
    // i.e. u64 pair (hg, hp) lives at k*32 + half*16 + hg*2 + p.
    {
        const int j = tid & 63, qg = tid >> 6;               // qg 0..7
        const int fj = ((j & 7) >> 2) * 32 + (j >> 3) * 4 + (((j & 7) >> 1) & 1) * 2 + (j & 1);
        for (int q = qg; q < 128; q += 8) {
            float4 w = *(const float4*)&W_hh[(h0 + j) * Hsz + 4 * q];
            Wt[(4*q+0)*64 + fj] = w.x;
            Wt[(4*q+1)*64 + fj] = w.y;
            Wt[(4*q+2)*64 + fj] = w.z;
            Wt[(4*q+3)*64 + fj] = w.w;
        }
    }

    // GEMM roles: ks 0..15 (32 k each), hg 0..7 (8 h-rows = 4 h-pairs), bg 0..3 (2 b)
    const int ks = tid >> 5;
    const int hg = (tid >> 2) & 7;
    const int bg = tid & 3;
    // Phase-2/epilogue roles: h = tid>>3, b = tid&7
    const int ph = tid >> 3, pb = tid & 7;
    const int hp = ph >> 1, par = ph & 1;
    const float invT = 1.0f / 512.0f;

    unsigned base_gen = 0;
    if (tid == 0) base_gen = *(volatile unsigned*)&g_pbar_gen[pod * 32];

    __syncthreads();   // Wt staged before first GEMM

    for (int t = 0; t < Tlen; t++) {
        // hs2/red overwrite is safe: phase-2 reads finished before the
        // pre-barrier sync of the previous step.
        if (t == 0) {
            // Fused hinit: hs2[k][b] = {h0[k], h0[k]}
            float v = h0g[tid];                      // tid == k
            u64 p; PACK2(p, v, v);
            ulonglong2 pp; pp.x = p; pp.y = p;
            ulonglong2* dst = (ulonglong2*)&hs2[tid * PB];
            dst[0] = pp; dst[1] = pp; dst[2] = pp; dst[3] = pp;
        } else {
            // Stage pod h slice (32KB of pairs): plain copy, no PACK needed
            const float4* hsrc = (const float4*)(g_h2[t & 1] + pod * (Hsz * PB));
            #pragma unroll
            for (int j2 = 0; j2 < 4; j2++) {
                int idx = tid + 512 * j2;                    // 2048 float4
                ((float4*)hs2)[idx] = __ldcg(hsrc + idx);
            }
        }
        // Prefetch xp for this thread's epilogue output (hidden by GEMM)
        const float xp = __ldg(&g_xp[(((size_t)t * PODS + pod) * Hsz + h0) * PB + tid]);
        __syncthreads();

        // GEMM slice: acc[4 hpairs][2 b] f32x2; per k: 3 LDS.128 + 8 FMA2
        u64 a0[2], a1[2], a2[2], a3[2];
        a0[0]=0; a0[1]=0; a1[0]=0; a1[1]=0; a2[0]=0; a2[1]=0; a3[0]=0; a3[1]=0;

        const u64* wr = &Wtu[(ks * 32) * 32 + hg * 2];
        const u64* hr = &hs2[(ks * 32) * PB + bg * 2];
        #pragma unroll 8
        for (int kk = 0; kk < 32; kk++) {
            ulonglong2 wA = *(const ulonglong2*)&wr[kk * 32];       // hp0, hp1
            ulonglong2 wB = *(const ulonglong2*)&wr[kk * 32 + 16];  // hp2, hp3
            ulonglong2 hv = *(const ulonglong2*)&hr[kk * PB];       // {b0,b0},{b1,b1}
            FMA2(a0[0], wA.x, hv.x); FMA2(a0[1], wA.x, hv.y);
            FMA2(a1[0], wA.y, hv.x); FMA2(a1[1], wA.y, hv.y);
            FMA2(a2[0], wB.x, hv.x); FMA2(a2[1], wB.x, hv.y);
            FMA2(a3[0], wB.y, hv.x); FMA2(a3[1], wB.y, hv.y);
        }
        // Store partials: red[ks][hg*4+hp][bg*2 + b], plain ST.64
        // (odd REDROW padding => rows not 16B-aligned; u64 stores are safe and
        //  land at the 2-phase/warp crossbar minimum)
        {
            u64* rb = &red[ks * REDSLAB + (hg * 4) * REDROW + bg * 2];
            rb[0]              = a0[0]; rb[1]              = a0[1];
            rb[REDROW]         = a1[0]; rb[REDROW + 1]     = a1[1];
            rb[2 * REDROW]     = a2[0]; rb[2 * REDROW + 1] = a2[1];
            rb[3 * REDROW]     = a3[0]; rb[3 * REDROW + 1] = a3[1];
        }
        __syncthreads();

        // Phase 2: reduce 16 K-splits, epilogue h_new = h + tanh(acc+xp)*invT
        {
            const float* rp = &redf[(hp * REDROW + pb) * 2 + par];
            float s0 = 0.f, s1 = 0.f, s2 = 0.f, s3 = 0.f;
            #pragma unroll
            for (int k2 = 0; k2 < 4; k2++) {
                s0 += rp[(4*k2+0) * (REDSLAB*2)];
                s1 += rp[(4*k2+1) * (REDSLAB*2)];
                s2 += rp[(4*k2+2) * (REDSLAB*2)];
                s3 += rp[(4*k2+3) * (REDSLAB*2)];
            }
            float v = (s0 + s1) + (s2 + s3);
            float hpv = hs2f[(h0 * PB + tid) * 2];   // .lo of replicated pair
            float hnew = hpv + tanhf(v + xp) * invT;
            u64 pv; PACK2(pv, hnew, hnew);
            g_h2[(t + 1) & 1][pod * (Hsz * PB) + h0 * PB + tid] = pv;
        }

        // Pod-local barrier (8 blocks, monotonic generation counter)
        __syncthreads();
        if (tid == 0) {
            __threadfence();
            unsigned target = base_gen + (unsigned)(t + 1);
            if (atomicAdd(&g_pbar_count[pod * 32], 1u) == PODB - 1) {
                atomicExch(&g_pbar_count[pod * 32], 0u);
                __threadfence();
                atomicExch(&g_pbar_gen[pod * 32], target);
            } else {
                while ((*(volatile unsigned*)&g_pbar_gen[pod * 32]) - base_gen < (unsigned)(t + 1)) { }
            }
        }
        __syncthreads();
    }

    // ---- Fused readout: out[b][o] = sum_k h_last[k][b]*W_out[o][k] + b_out[o]
    const int o0 = ht * 32;
    {
        // Final h (T=512 even -> parity 0); pod-synced by the last barrier.
        const float4* hsrc = (const float4*)(g_h2[0] + pod * (Hsz * PB));
        #pragma unroll
        for (int j2 = 0; j2 < 4; j2++) {
            int idx = tid + 512 * j2;
            ((float4*)hs2)[idx] = __ldcg(hsrc + idx);
        }
        // W_out slice transposed into (freed) Wt region: plain Wo[k][32]
        const int lane_j = tid & 31, qg = tid >> 5;          // qg 0..15
        for (int q = qg; q < 128; q += 16) {
            float4 w = *(const float4*)&W_out[(o0 + lane_j) * Hsz + 4 * q];
            Wt[(4*q+0)*32 + lane_j] = w.x;
            Wt[(4*q+1)*32 + lane_j] = w.y;
            Wt[(4*q+2)*32 + lane_j] = w.z;
            Wt[(4*q+3)*32 + lane_j] = w.w;
        }
    }
    __syncthreads();
    if (tid < 256) {
        const int b_ = tid & 7, og = tid >> 3;       // og 0..31
        float acc = 0.f;
        #pragma unroll 8
        for (int k = 0; k < Hsz; k++) {
            acc += hs2f[(k * PB + b_) * 2] * Wt[k * 32 + og];
        }
        out[(pod * PB + b_) * Osz + o0 + og] = acc + b_out[o0 + og];
    }
}

// ---------------------------------------------------------------------------
extern "C" void kernel_launch(void* const* d_in, const int* in_sizes, int n_in,
                              void* d_out, int out_size)
{
    const float* inputs = (const float*)d_in[0];
    const float* W_ih   = (const float*)d_in[1];
    const float* b_ih   = (const float*)d_in[2];
    const float* W_hh   = (const float*)d_in[3];
    const float* b_hh   = (const float*)d_in[4];
    const float* W_out  = (const float*)d_in[5];
    const float* b_out  = (const float*)d_in[6];
    const float* h0     = (const float*)d_in[7];
    float* out = (float*)d_out;

    const int SMEM_XP  = 8192 * 4 + 2 * 16 * XSROW * 8 + 1024 * 8;         // 73856 B
    const int SMEM_RNN = Hsz * 64 * 4 + Hsz * PB * 8 + 16 * REDSLAB * 8;   // 197632 B
    cudaFuncSetAttribute(xp_kernel,  cudaFuncAttributeMaxDynamicSharedMemorySize, SMEM_XP);
    cudaFuncSetAttribute(rnn_kernel, cudaFuncAttributeMaxDynamicSharedMemorySize, SMEM_RNN);

    xp_kernel<<<dim3(Tlen / TQ, NBT, Hsz / 32), 256, SMEM_XP>>>(inputs, W_ih, b_ih, b_hh);
    rnn_kernel<<<PODS * PODB, 512, SMEM_RNN>>>(W_hh, h0, W_out, b_out, out);
}

// round 16
// speedup vs baseline: 1.6909x; 1.1189x over previous
#include <cuda_runtime.h>
#include <math.h>

// Problem dims (fixed)
#define Bsz   128
#define Tlen  512
#define Isz   256
#define Hsz   512
#define Osz   256

// Pod decomposition: 16 independent pods x 8 blocks; each pod owns 8 batches,
// each block owns 64 h-rows of W_hh (128KB fp32 in smem).
#define PODS  16
#define PODB  8      // blocks per pod
#define PB    8      // batches per pod
#define NBT   8      // xp batch tiles (of 16)

// Packed f32x2 helpers (ptxas never emits FFMA2 from C++; inline PTX required)
#define FMA2(acc, a, b) \
    asm("fma.rn.f32x2 %0, %1, %2, %0;" : "+l"(acc) : "l"(a), "l"(b))
#define ADD2(d, a, b) \
    asm("add.rn.f32x2 %0, %1, %2;" : "=l"(d) : "l"(a), "l"(b))
#define PACK2(d, lo, hi) \
    asm("mov.b64 %0, {%1, %2};" : "=l"(d) : "f"(lo), "f"(hi))
#define UNPACK2(lo, hi, v) \
    asm("mov.b64 {%0, %1}, %2;" : "=f"(lo), "=f"(hi) : "l"(v))

typedef unsigned long long u64;

__device__ __forceinline__ unsigned ldv(const unsigned* p) {
    unsigned v;
    asm volatile("ld.volatile.global.u32 %0, [%1];" : "=r"(v) : "l"(p));
    return v;
}

// Scratch (device globals; no runtime allocation)
__device__ float    g_xp[(size_t)Tlen * PODS * Hsz * PB]; // [t][pod][h][8]
__device__ u64      g_h2[2][PODS * Hsz * PB];             // [parity][pod][k][8] as {h,h}
__device__ unsigned g_flag[PODS * PODB * 32];             // 128B-padded per (pod,chunk)

// ---------------------------------------------------------------------------
// x_proj: xp[t][pod][h][b] = sum_i inputs[b][t][i]*W_ih[h][i] + b_ih[h]+b_hh[h]
// Block (0,0,0) also zeroes the producer flags (stream-ordered before rnn).
// ---------------------------------------------------------------------------
#define TQ  8
#define XSROW 257

__global__ void __launch_bounds__(256) xp_kernel(
    const float* __restrict__ inputs, const float* __restrict__ W_ih,
    const float* __restrict__ b_ih,   const float* __restrict__ b_hh)
{
    extern __shared__ float smem[];
    float* Wt  = smem;                              // [256][32]: Wt[i][j]=W_ih[h0+j][i]
    u64*   xs2 = (u64*)(smem + 8192);               // [16][257]: xs2[b][i]={x,x}
    u64*   red = (u64*)(smem + 8192 + 2 * 16 * XSROW);  // [4][16][16]
    const u64* Wtu = (const u64*)Wt;

    const int tq = blockIdx.x, bt = blockIdx.y, ht = blockIdx.z;
    const int h0 = ht * 32, b0 = bt * 16;
    const int tid = threadIdx.x;

    // Zero rnn producer flags (one block; kernel boundary orders vs rnn)
    if (tq == 0 && bt == 0 && ht == 0) {
        for (int i = tid; i < PODS * PODB * 32; i += 256) g_flag[i] = 0;
    }

    // Stage W_ih tile transposed (once)
    {
        const int lane_j = tid & 31, qb = tid >> 5;          // qb 0..7
        for (int r = 0; r < 8; r++) {
            int q = qb + 8 * r;                              // 0..63
            float4 w = *(const float4*)&W_ih[(h0 + lane_j) * Isz + 4 * q];
            Wt[(4*q+0)*32 + lane_j] = w.x;
            Wt[(4*q+1)*32 + lane_j] = w.y;
            Wt[(4*q+2)*32 + lane_j] = w.z;
            Wt[(4*q+3)*32 + lane_j] = w.w;
        }
    }

    const int bg = tid & 7, hg = (tid >> 3) & 7, is = tid >> 6;  // I-split 4
    const int pb = tid & 15, php = tid >> 4;                     // phase-2 roles
    const int pod = bt * 2 + (pb >> 3), bi = pb & 7;
    const float pbias0 = b_ih[h0 + php*2 + 0] + b_hh[h0 + php*2 + 0];
    const float pbias1 = b_ih[h0 + php*2 + 1] + b_hh[h0 + php*2 + 1];

    for (int tt = 0; tt < TQ; tt++) {
        const int t = tq * TQ + tt;
        __syncthreads();   // xs2/red reuse; covers Wt on first iter
        for (int j = 0; j < 4; j++) {
            int idx = tid + 256 * j;                 // 1024 float4 loads
            int r = idx >> 6, q = idx & 63;
            float4 x = *(const float4*)&inputs[((size_t)(b0 + r) * Tlen + t) * Isz + 4 * q];
            u64 p0, p1, p2, p3;
            PACK2(p0, x.x, x.x); PACK2(p1, x.y, x.y);
            PACK2(p2, x.z, x.z); PACK2(p3, x.w, x.w);
            u64* dst = &xs2[r * XSROW + 4 * q];
            dst[0] = p0; dst[1] = p1; dst[2] = p2; dst[3] = p3;
        }
        __syncthreads();

        u64 a00 = 0, a10 = 0, a01 = 0, a11 = 0;
        const u64* xr0 = &xs2[(2 * bg + 0) * XSROW + is * 64];
        const u64* xr1 = &xs2[(2 * bg + 1) * XSROW + is * 64];
        const u64* wr  = &Wtu[(is * 64) * 16 + hg * 2];
        #pragma unroll 8
        for (int ii = 0; ii < 64; ii++) {
            ulonglong2 w = *(const ulonglong2*)&wr[ii * 16];
            u64 x0 = xr0[ii];
            u64 x1 = xr1[ii];
            FMA2(a00, w.x, x0);
            FMA2(a10, w.y, x0);
            FMA2(a01, w.x, x1);
            FMA2(a11, w.y, x1);
        }
        u64* rb = &red[is * 256 + (hg * 2) * 16 + bg * 2];
        rb[0]  = a00;
        rb[16] = a10;
        rb[1]  = a01;
        rb[17] = a11;
        __syncthreads();

        u64 s, u;
        ADD2(s, red[0*256 + php*16 + pb], red[1*256 + php*16 + pb]);
        ADD2(u, red[2*256 + php*16 + pb], red[3*256 + php*16 + pb]);
        ADD2(s, s, u);
        float v0, v1; UNPACK2(v0, v1, s);
        float* dst = &g_xp[(((size_t)t * PODS + pod) * Hsz + h0 + php * 2) * PB + bi];
        dst[0]  = v0 + pbias0;
        dst[PB] = v1 + pbias1;
    }
}

// ---------------------------------------------------------------------------
// Persistent recurrence, dataflow-synced (per-chunk producer flags, no pod
// barrier). 128 blocks = 16 pods x 8; 512 threads.
// Warp ks consumes only chunk ks/2 (64 h-rows) -> waits only on that flag.
// Own chunk lives in smem (epilogue writes hs2 directly).
// GEMM per k: 3 LDS.128 + 8 FMA2. 2 syncthreads per step, no pod barrier.
// smem: Wt[512][64] half-split (128KB) + hs2[512][8] u64 (32KB) + red (36KB)
// ---------------------------------------------------------------------------
#define REDROW 9                       // u64 per hp-row (padded: kills 8-way conflict)
#define REDSLAB (32 * REDROW)          // 288 u64 per ks slab

__global__ void __launch_bounds__(512) rnn_kernel(
    const float* __restrict__ W_hh, const float* __restrict__ h0g,
    const float* __restrict__ W_out, const float* __restrict__ b_out,
    float* __restrict__ out)
{
    extern __shared__ float smem[];
    float* Wt  = smem;                          // [512][64] half-split (see below)
    u64*   hs2 = (u64*)(smem + Hsz * 64);       // [512][8]: {h[k][b], h[k][b]}
    u64*   red = (u64*)(smem + Hsz * 64 + Hsz * PB * 2);  // [16][32][9]
    const u64* Wtu = (const u64*)Wt;
    float* hs2f = (float*)hs2;
    const float* redf = (const float*)red;

    const int blk = blockIdx.x;
    const int pod = blk >> 3, ht = blk & 7;
    const int h0 = ht * 64;
    const int tid = threadIdx.x;
    const int lane = tid & 31;

    // Stage W_hh slice once. Per-k float layout (warp w-load = contiguous 128B):
    //   u64 pair (hg, hp) lives at k*32 + half*16 + hg*2 + p
    {
        const int j = tid & 63, qg = tid >> 6;               // qg 0..7
        const int fj = ((j & 7) >> 2) * 32 + (j >> 3) * 4 + (((j & 7) >> 1) & 1) * 2 + (j & 1);
        for (int q = qg; q < 128; q += 8) {
            float4 w = *(const float4*)&W_hh[(h0 + j) * Hsz + 4 * q];
            Wt[(4*q+0)*64 + fj] = w.x;
            Wt[(4*q+1)*64 + fj] = w.y;
            Wt[(4*q+2)*64 + fj] = w.z;
            Wt[(4*q+3)*64 + fj] = w.w;
        }
    }

    // GEMM roles: ks = warp 0..15 (32 k each), hg 0..7, bg 0..3 (2 b)
    const int ks = tid >> 5;
    const int hg = (tid >> 2) & 7;
    const int bg = tid & 3;
    const int chunk = ks >> 1;                   // producer block of this k-range
    const unsigned* flagp = &g_flag[(pod * PODB + chunk) * 32];
    unsigned* myflag = &g_flag[(pod * PODB + ht) * 32];
    const bool remote = (chunk != ht);
    // Phase-2/epilogue roles: h = tid>>3, b = tid&7
    const int ph = tid >> 3, pb = tid & 7;
    const int hp = ph >> 1, par = ph & 1;
    const float invT = 1.0f / 512.0f;

    // Fused hinit: hs2[k][b] = {h0[k], h0[k]} (covers all chunks at t=0)
    {
        float v = h0g[tid];                      // tid == k
        u64 p; PACK2(p, v, v);
        ulonglong2 pp; pp.x = p; pp.y = p;
        ulonglong2* dst = (ulonglong2*)&hs2[tid * PB];
        dst[0] = pp; dst[1] = pp; dst[2] = pp; dst[3] = pp;
    }
    __syncthreads();   // hinit + Wt staged

    for (int t = 0; t < Tlen; t++) {
        // Prefetch xp early (independent of staging)
        const float xp = __ldg(&g_xp[(((size_t)t * PODS + pod) * Hsz + h0) * PB + tid]);

        // Per-warp: wait on producer flag, stage own 2KB slice of h_t.
        // Own-chunk warps skip: epilogue of t-1 wrote hs2 directly.
        if (t > 0 && remote) {
            if (lane == 0) {
                while ((int)ldv(flagp) < t) { }
            }
            __syncwarp();
            const float4* src = (const float4*)(g_h2[t & 1] + pod * (Hsz * PB) + ks * 256);
            float4* dst = (float4*)(hs2 + ks * 256);
            #pragma unroll
            for (int j = 0; j < 4; j++)
                dst[j * 32 + lane] = __ldcg(src + j * 32 + lane);
        }

        // GEMM slice: acc[4 hpairs][2 b] f32x2; per k: 3 LDS.128 + 8 FMA2
        u64 a0[2], a1[2], a2[2], a3[2];
        a0[0]=0; a0[1]=0; a1[0]=0; a1[1]=0; a2[0]=0; a2[1]=0; a3[0]=0; a3[1]=0;

        const u64* wr = &Wtu[(ks * 32) * 32 + hg * 2];
        const u64* hr = &hs2[(ks * 32) * PB + bg * 2];
        #pragma unroll 8
        for (int kk = 0; kk < 32; kk++) {
            ulonglong2 wA = *(const ulonglong2*)&wr[kk * 32];       // hp0, hp1
            ulonglong2 wB = *(const ulonglong2*)&wr[kk * 32 + 16];  // hp2, hp3
            ulonglong2 hv = *(const ulonglong2*)&hr[kk * PB];       // {b0,b0},{b1,b1}
            FMA2(a0[0], wA.x, hv.x); FMA2(a0[1], wA.x, hv.y);
            FMA2(a1[0], wA.y, hv.x); FMA2(a1[1], wA.y, hv.y);
            FMA2(a2[0], wB.x, hv.x); FMA2(a2[1], wB.x, hv.y);
            FMA2(a3[0], wB.y, hv.x); FMA2(a3[1], wB.y, hv.y);
        }
        // Store partials: red[ks][hg*4+hp][bg*2 + b], plain ST.64
        {
            u64* rb = &red[ks * REDSLAB + (hg * 4) * REDROW + bg * 2];
            rb[0]              = a0[0]; rb[1]              = a0[1];
            rb[REDROW]         = a1[0]; rb[REDROW + 1]     = a1[1];
            rb[2 * REDROW]     = a2[0]; rb[2 * REDROW + 1] = a2[1];
            rb[3 * REDROW]     = a3[0]; rb[3 * REDROW + 1] = a3[1];
        }
        __syncthreads();

        // Phase 2: reduce 16 K-splits, epilogue h_new = h + tanh(acc+xp)*invT
        {
            const float* rp = &redf[(hp * REDROW + pb) * 2 + par];
            float s0 = 0.f, s1 = 0.f, s2 = 0.f, s3 = 0.f;
            #pragma unroll
            for (int k2 = 0; k2 < 4; k2++) {
                s0 += rp[(4*k2+0) * (REDSLAB*2)];
                s1 += rp[(4*k2+1) * (REDSLAB*2)];
                s2 += rp[(4*k2+2) * (REDSLAB*2)];
                s3 += rp[(4*k2+3) * (REDSLAB*2)];
            }
            float v = (s0 + s1) + (s2 + s3);
            float hpv = hs2f[(h0 * PB + tid) * 2];   // .lo of replicated pair (own chunk)
            float hnew = hpv + tanhf(v + xp) * invT;
            u64 pv; PACK2(pv, hnew, hnew);
            // Publish to consumers (global, 2-deep parity) and to own hs2 region
            g_h2[(t + 1) & 1][pod * (Hsz * PB) + h0 * PB + tid] = pv;
            hs2[h0 * PB + tid] = pv;
        }

        __threadfence();   // release: order h stores before flag publish
        __syncthreads();
        if (tid == 0) atomicExch(myflag, (unsigned)(t + 1));
    }

    // ---- Fused readout: out[b][o] = sum_k h_last[k][b]*W_out[o][k] + b_out[o]
    // Need h_512 (parity 0) for all chunks: own already in hs2; stage remote.
    if (remote) {
        if (lane == 0) {
            while ((int)ldv(flagp) < Tlen) { }
        }
        __syncwarp();
        const float4* src = (const float4*)(g_h2[0] + pod * (Hsz * PB) + ks * 256);
        float4* dst = (float4*)(hs2 + ks * 256);
        #pragma unroll
        for (int j = 0; j < 4; j++)
            dst[j * 32 + lane] = __ldcg(src + j * 32 + lane);
    }
    const int o0 = ht * 32;
    {
        // W_out slice transposed into (freed) Wt region: plain Wo[k][32]
        const int lane_j = tid & 31, qg = tid >> 5;          // qg 0..15
        for (int q = qg; q < 128; q += 16) {
            float4 w = *(const float4*)&W_out[(o0 + lane_j) * Hsz + 4 * q];
            Wt[(4*q+0)*32 + lane_j] = w.x;
            Wt[(4*q+1)*32 + lane_j] = w.y;
            Wt[(4*q+2)*32 + lane_j] = w.z;
            Wt[(4*q+3)*32 + lane_j] = w.w;
        }
    }
    __syncthreads();
    if (tid < 256) {
        const int b_ = tid & 7, og = tid >> 3;       // og 0..31
        float acc = 0.f;
        #pragma unroll 8
        for (int k = 0; k < Hsz; k++) {
            acc += hs2f[(k * PB + b_) * 2] * Wt[k * 32 + og];
        }
        out[(pod * PB + b_) * Osz + o0 + og] = acc + b_out[o0 + og];
    }
}

// ---------------------------------------------------------------------------
extern "C" void kernel_launch(void* const* d_in, const int* in_sizes, int n_in,
                              void* d_out, int out_size)
{
    const float* inputs = (const float*)d_in[0];
    const float* W_ih   = (const float*)d_in[1];
    const float* b_ih   = (const float*)d_in[2];
    const float* W_hh   = (const float*)d_in[3];
    const float* b_hh   = (const float*)d_in[4];
    const float* W_out  = (const float*)d_in[5];
    const float* b_out  = (const float*)d_in[6];
    const float* h0     = (const float*)d_in[7];
    float* out = (float*)d_out;

    const int SMEM_XP  = 8192 * 4 + 2 * 16 * XSROW * 8 + 1024 * 8;         // 73856 B
    const int SMEM_RNN = Hsz * 64 * 4 + Hsz * PB * 8 + 16 * REDSLAB * 8;   // 197632 B
    cudaFuncSetAttribute(xp_kernel,  cudaFuncAttributeMaxDynamicSharedMemorySize, SMEM_XP);
    cudaFuncSetAttribute(rnn_kernel, cudaFuncAttributeMaxDynamicSharedMemorySize, SMEM_RNN);

    xp_kernel<<<dim3(Tlen / TQ, NBT, Hsz / 32), 256, SMEM_XP>>>(inputs, W_ih, b_ih, b_hh);
    rnn_kernel<<<PODS * PODB, 512, SMEM_RNN>>>(W_hh, h0, W_out, b_out, out);
}